// round 3
// baseline (speedup 1.0000x reference)
#include <cuda_runtime.h>
#include <math.h>

// ---------------- problem constants ----------------
#define BB 2
#define CC 96
#define C2 192
#define HH 256
#define WW 256
#define PIX (HH*WW)          // 65536
#define NP 260               // padded size (256 + 2*2)
#define SPECN (NP*NP)        // 67600
#define NCH (BB*C2)          // 384

// ---------------- scratch (static device globals; no runtime alloc) -------------
__device__ float  g_ln[(size_t)BB*CC*PIX];       // 50 MB
__device__ float  g_h1[(size_t)BB*C2*PIX];       // 100 MB
__device__ float  g_x2[(size_t)BB*CC*PIX];       // 50 MB
__device__ float2 g_spec[(size_t)NCH*SPECN];     // 208 MB
__device__ float2 g_tw[NP];                      // e^{-2*pi*i*n/260}
__device__ float  g_w9[C2*9];                    // softmaxed 3x3 kernels
__device__ float  g_sig[C2];                     // sigma per channel

// compile-time buffer selector: 0=g_ln, 1=g_h1, 2=g_x2, -1=external pointer
template<int SEL>
__device__ __forceinline__ float* gbuf(const float* ext){
    if (SEL == 0) return g_ln;
    if (SEL == 1) return g_h1;
    if (SEL == 2) return g_x2;
    return (float*)ext;
}

__device__ __forceinline__ float gelu_f(float x){
    return 0.5f * x * (1.0f + erff(x * 0.70710678118654752440f));
}

// ---------------- init: twiddles + per-channel softmax/sigma ----------------
__global__ void init_kernel(const float* __restrict__ conv_w,
                            const float* __restrict__ conv_sigma){
    int tid = threadIdx.x;
    if (tid < NP){
        double ang = -2.0 * 3.14159265358979323846 * (double)tid / (double)NP;
        double s, c;
        sincos(ang, &s, &c);
        g_tw[tid] = make_float2((float)c, (float)s);
    }
    for (int ch = tid; ch < C2; ch += blockDim.x){
        float w[9];
        float m = -1e30f;
        #pragma unroll
        for (int i=0;i<9;i++){ w[i] = conv_w[ch*9+i]; m = fmaxf(m, w[i]); }
        float ssum = 0.f;
        #pragma unroll
        for (int i=0;i<9;i++){ w[i] = expf(w[i]-m); ssum += w[i]; }
        float inv = 1.f/ssum;
        #pragma unroll
        for (int i=0;i<9;i++) g_w9[ch*9+i] = w[i]*inv;
        float sp = conv_sigma[ch];
        g_sig[ch] = 1.f/(1.f + expf(9.f - sp)) + 1e-5f;
    }
}

// ---------------- channels-first LayerNorm: src(SEL or ext) -> g_ln ----------------
template<int XSEL>
__global__ void ln_kernel(const float* __restrict__ xext,
                          const float* __restrict__ w,
                          const float* __restrict__ b){
    const float* x = gbuf<XSEL>(xext);
    int pi = blockIdx.x*blockDim.x + threadIdx.x;
    if (pi >= BB*PIX) return;
    int bb = pi >> 16;
    int p  = pi & (PIX-1);
    const float* xb = x + (size_t)bb*CC*PIX + p;
    float s=0.f, s2=0.f;
    #pragma unroll 4
    for (int c=0;c<CC;c++){ float v = xb[(size_t)c*PIX]; s += v; s2 += v*v; }
    float mu  = s * (1.f/CC);
    float var = s2 * (1.f/CC) - mu*mu;
    float inv = rsqrtf(var + 1e-5f);
    float* ob = g_ln + (size_t)bb*CC*PIX + p;
    #pragma unroll 4
    for (int c=0;c<CC;c++){
        float v = xb[(size_t)c*PIX];
        ob[(size_t)c*PIX] = (v-mu)*inv*w[c] + b[c];
    }
}

// ---------------- 1x1 conv as tiled SGEMM  out[o,p] = sum_c W[o,c]*X[c,p] ----------------
// MODE 0: out = gelu(acc + bias)
// MODE 1: out = acc + bias + res
template<int CIN, int COUT, int MODE, int XSEL, int RSEL, int OSEL>
__global__ void gemm_kernel(const float* __restrict__ Xext,
                            const float* __restrict__ W,
                            const float* __restrict__ bias,
                            const float* __restrict__ Rext,
                            float* __restrict__ Oext){
    const float* X   = gbuf<XSEL>(Xext);
    const float* res = gbuf<RSEL>(Rext);
    float*       out = gbuf<OSEL>(Oext);
    const int TP=128, TO=48, KC=8;
    __shared__ float Xs[KC][TP];
    __shared__ float Ws[TO][KC];
    int bb = blockIdx.z;
    int p0 = blockIdx.x*TP;
    int o0 = blockIdx.y*TO;
    int tid = threadIdx.x;       // 256
    int lp = tid & 31;
    int og = tid >> 5;           // 0..7
    float acc[4][6];
    #pragma unroll
    for (int i=0;i<4;i++)
        #pragma unroll
        for (int j=0;j<6;j++) acc[i][j]=0.f;

    const float* Xb = X + (size_t)bb*CIN*PIX + p0;
    for (int kc=0; kc<CIN; kc+=KC){
        #pragma unroll
        for (int i=0;i<(KC*TP)/256;i++){
            int idx = tid + 256*i; int k = idx/TP, pp = idx%TP;
            Xs[k][pp] = Xb[(size_t)(kc+k)*PIX + pp];
        }
        for (int idx=tid; idx<TO*KC; idx+=256){
            int o = idx/KC, k = idx%KC;
            Ws[o][k] = W[(o0+o)*CIN + kc + k];
        }
        __syncthreads();
        #pragma unroll
        for (int k=0;k<KC;k++){
            float xv[4], wv[6];
            #pragma unroll
            for (int i=0;i<4;i++) xv[i] = Xs[k][lp + 32*i];
            #pragma unroll
            for (int j=0;j<6;j++) wv[j] = Ws[og*6+j][k];
            #pragma unroll
            for (int i=0;i<4;i++)
                #pragma unroll
                for (int j=0;j<6;j++) acc[i][j] += xv[i]*wv[j];
        }
        __syncthreads();
    }
    #pragma unroll
    for (int j=0;j<6;j++){
        int o = o0 + og*6 + j;
        float bj = bias[o];
        #pragma unroll
        for (int i=0;i<4;i++){
            int p = p0 + lp + 32*i;
            size_t oidx = ((size_t)(bb*COUT + o))*PIX + p;
            float v = acc[i][j] + bj;
            if (MODE==0) v = gelu_f(v);
            else         v += res[oidx];
            out[oidx] = v;
        }
    }
}

// ---------------- FFT pieces: 260 = 13 * 20 Cooley-Tukey ----------------
// Stage A: A[n2][k1] = sum_{n1<20} x[13*n1+n2] * W260^{13*n1*k1}
// Stage C: X[k]      = sum_{n2<13} A[n2][k mod 20] * W260^{n2*k}

// forward FFT of each padded row of g_h1 (replicate padding on the fly, real input)
__global__ void fft_rows_fwd(){
    int prow = blockIdx.x;   // 0..259
    int ch   = blockIdx.y;   // 0..383
    __shared__ float  xin[NP];
    __shared__ float2 As[NP];
    __shared__ float2 tws[NP];
    int tid = threadIdx.x;   // 64
    for (int i=tid;i<NP;i+=64) tws[i] = g_tw[i];
    int srow = min(max(prow-2,0),HH-1);
    const float* rowp = g_h1 + ((size_t)ch*HH + srow)*WW;
    for (int i=tid;i<NP;i+=64){
        int sc = min(max(i-2,0),WW-1);
        xin[i] = rowp[sc];
    }
    __syncthreads();
    for (int o=tid;o<NP;o+=64){
        int n2 = o/20, k1 = o%20;
        int step = (13*k1) % NP;
        float sx=0.f, sy=0.f; int ti=0;
        #pragma unroll
        for (int n1=0;n1<20;n1++){
            float v = xin[13*n1 + n2];
            float2 t = tws[ti];
            sx += v*t.x; sy += v*t.y;
            ti += step; if (ti>=NP) ti -= NP;
        }
        As[o] = make_float2(sx,sy);
    }
    __syncthreads();
    float2* orow = g_spec + (size_t)ch*SPECN + (size_t)prow*NP;
    for (int k=tid;k<NP;k+=64){
        int k1 = k % 20;
        float sx=0.f, sy=0.f; int ti=0;
        #pragma unroll
        for (int n2=0;n2<13;n2++){
            float2 a = As[n2*20 + k1];
            float2 t = tws[ti];
            sx += a.x*t.x - a.y*t.y;
            sy += a.x*t.y + a.y*t.x;
            ti += k; if (ti>=NP) ti -= NP;
        }
        orow[k] = make_float2(sx,sy);
    }
}

// column FFT of g_spec (in place), DIR=+1 forward, DIR=-1 inverse (conj, no scaling)
template<int DIR>
__global__ void fft_cols(){
    int cg = blockIdx.x;     // 0..64, 4 columns each
    int ch = blockIdx.y;
    __shared__ float2 cs[4][NP];
    __shared__ float2 As[4][NP];
    __shared__ float2 tws[NP];
    int tid = threadIdx.x;   // 128
    for (int i=tid;i<NP;i+=128) tws[i] = g_tw[i];
    float2* base = g_spec + (size_t)ch*SPECN + cg*4;
    for (int idx=tid; idx<NP*4; idx+=128){
        int r = idx>>2, c = idx&3;
        cs[c][r] = base[(size_t)r*NP + c];
    }
    __syncthreads();
    int c = tid >> 5;        // warp -> column
    int lane = tid & 31;
    for (int o=lane;o<NP;o+=32){
        int n2=o/20, k1=o%20, step=(13*k1)%NP;
        float sx=0.f, sy=0.f; int ti=0;
        #pragma unroll
        for (int n1=0;n1<20;n1++){
            float2 v = cs[c][13*n1+n2];
            float2 t = tws[ti];
            float tyy = (DIR>0)? t.y : -t.y;
            sx += v.x*t.x - v.y*tyy;
            sy += v.x*tyy + v.y*t.x;
            ti += step; if (ti>=NP) ti-=NP;
        }
        As[c][o] = make_float2(sx,sy);
    }
    __syncthreads();
    for (int k=lane;k<NP;k+=32){
        int k1=k%20;
        float sx=0.f, sy=0.f; int ti=0;
        #pragma unroll
        for (int n2=0;n2<13;n2++){
            float2 a = As[c][n2*20+k1];
            float2 t = tws[ti];
            float tyy = (DIR>0)? t.y : -t.y;
            sx += a.x*t.x - a.y*tyy;
            sy += a.x*tyy + a.y*t.x;
            ti += k; if (ti>=NP) ti-=NP;
        }
        cs[c][k] = make_float2(sx,sy);
    }
    __syncthreads();
    for (int idx=tid; idx<NP*4; idx+=128){
        int r=idx>>2, cc=idx&3;
        base[(size_t)r*NP+cc] = cs[cc][r];
    }
}

// pointwise: spec *= (conj(FB)+sigma)/(|FB|^2+sigma) / 67600
__global__ void pointwise_hf(){
    __shared__ float2 tws[NP];
    for (int i=threadIdx.x;i<NP;i+=blockDim.x) tws[i]=g_tw[i];
    __syncthreads();
    long long idx = (long long)blockIdx.x*blockDim.x + threadIdx.x;
    const long long total = (long long)NCH*SPECN;
    if (idx >= total) return;
    int ch  = (int)(idx / SPECN);
    int rem = (int)(idx % SPECN);
    int u = rem / NP, v = rem % NP;
    int c2 = ch % C2;
    const float* w = g_w9 + c2*9;
    float sg = g_sig[c2];
    float fbx=0.f, fby=0.f;
    #pragma unroll
    for (int p=0;p<3;p++){
        #pragma unroll
        for (int q=0;q<3;q++){
            int m = u*(p-1) + v*(q-1);
            m %= NP; if (m<0) m += NP;
            float2 t = tws[m];
            float wv = w[p*3+q];
            fbx += wv*t.x; fby += wv*t.y;
        }
    }
    float denom = fbx*fbx + fby*fby + sg;
    float scale = 1.0f/((float)SPECN * denom);
    float hx = (fbx + sg)*scale;
    float hy = (-fby)*scale;
    float2 s = g_spec[idx];
    g_spec[idx] = make_float2(s.x*hx - s.y*hy, s.x*hy + s.y*hx);
}

// inverse FFT of each needed row + crop + gelu -> g_h1 (real)
__global__ void fft_rows_inv_gelu(){
    int orow = blockIdx.x;   // 0..255
    int ch   = blockIdx.y;
    int prow = orow + 2;
    __shared__ float2 xin[NP];
    __shared__ float2 As[NP];
    __shared__ float2 tws[NP];
    int tid = threadIdx.x;   // 64
    for (int i=tid;i<NP;i+=64) tws[i]=g_tw[i];
    const float2* row = g_spec + (size_t)ch*SPECN + (size_t)prow*NP;
    for (int i=tid;i<NP;i+=64) xin[i] = row[i];
    __syncthreads();
    for (int o=tid;o<NP;o+=64){
        int n2=o/20, k1=o%20, step=(13*k1)%NP;
        float sx=0.f, sy=0.f; int ti=0;
        #pragma unroll
        for (int n1=0;n1<20;n1++){
            float2 v = xin[13*n1+n2];
            float2 t = tws[ti];      // inverse: conj
            sx += v.x*t.x + v.y*t.y;
            sy += v.y*t.x - v.x*t.y;
            ti+=step; if (ti>=NP) ti-=NP;
        }
        As[o]=make_float2(sx,sy);
    }
    __syncthreads();
    float* outp = g_h1 + ((size_t)ch*HH + orow)*WW;
    for (int kk=tid;kk<WW;kk+=64){
        int k = kk+2;
        int k1=k%20;
        float sx=0.f; int ti=0;
        #pragma unroll
        for (int n2=0;n2<13;n2++){
            float2 a = As[n2*20+k1];
            float2 t = tws[ti];      // inverse: conj; only real part needed
            sx += a.x*t.x + a.y*t.y;
            ti += k; if (ti>=NP) ti-=NP;
        }
        outp[kk] = gelu_f(sx);
    }
}

// ---------------- launcher: kernel launches ONLY ----------------
extern "C" void kernel_launch(void* const* d_in, const int* in_sizes, int n_in,
                              void* d_out, int out_size){
    const float* x         = (const float*)d_in[0];
    const float* ln1_w     = (const float*)d_in[1];
    const float* ln1_b     = (const float*)d_in[2];
    const float* w1a       = (const float*)d_in[3];
    const float* b1a       = (const float*)d_in[4];
    const float* conv_w    = (const float*)d_in[5];
    const float* conv_sig  = (const float*)d_in[6];
    const float* w1b       = (const float*)d_in[7];
    const float* b1b       = (const float*)d_in[8];
    const float* ln2_w     = (const float*)d_in[9];
    const float* ln2_b     = (const float*)d_in[10];
    const float* w2a       = (const float*)d_in[11];
    const float* b2a       = (const float*)d_in[12];
    const float* w2b       = (const float*)d_in[13];
    const float* b2b       = (const float*)d_in[14];
    float* out = (float*)d_out;

    init_kernel<<<1, 260>>>(conv_w, conv_sig);

    // branch 1: LN -> expand+gelu -> converse2d -> gelu -> project + residual
    ln_kernel<-1><<<(BB*PIX)/256, 256>>>(x, ln1_w, ln1_b);
    gemm_kernel<CC, C2, 0, 0, 0, 1><<<dim3(PIX/128, C2/48, BB), 256>>>(
        nullptr, w1a, b1a, nullptr, nullptr);

    fft_rows_fwd<<<dim3(NP, NCH), 64>>>();
    fft_cols<1><<<dim3(NP/4, NCH), 128>>>();
    {
        long long total = (long long)NCH*SPECN;
        int blocks = (int)((total + 255)/256);
        pointwise_hf<<<blocks, 256>>>();
    }
    fft_cols<-1><<<dim3(NP/4, NCH), 128>>>();
    fft_rows_inv_gelu<<<dim3(HH, NCH), 64>>>();

    gemm_kernel<C2, CC, 1, 1, -1, 2><<<dim3(PIX/128, CC/48, BB), 256>>>(
        nullptr, w1b, b1b, x, nullptr);

    // branch 2: LN -> expand+gelu -> project + residual
    ln_kernel<2><<<(BB*PIX)/256, 256>>>(nullptr, ln2_w, ln2_b);
    gemm_kernel<CC, C2, 0, 0, 0, 1><<<dim3(PIX/128, C2/48, BB), 256>>>(
        nullptr, w2a, b2a, nullptr, nullptr);
    gemm_kernel<C2, CC, 1, 1, 2, -1><<<dim3(PIX/128, CC/48, BB), 256>>>(
        nullptr, w2b, b2b, nullptr, out);
}

// round 5
// speedup vs baseline: 1.9659x; 1.9659x over previous
#include <cuda_runtime.h>
#include <math.h>

// ---------------- problem constants ----------------
#define BB 2
#define CC 96
#define C2 192
#define HH 256
#define WW 256
#define PIX (HH*WW)          // 65536
#define NP 260               // padded size (256 + 2*2)
#define SW 132               // spectral row stride (131 stored, Hermitian half)
#define NCH (BB*C2)          // 384
#define SPECN_F 67600.0f     // 260*260

// ---------------- scratch (static device globals; no runtime alloc) -------------
__device__ float  g_ln[(size_t)BB*CC*PIX];
__device__ float  g_h1[(size_t)BB*C2*PIX];
__device__ float  g_x2[(size_t)BB*CC*PIX];
__device__ float2 g_spec[(size_t)NCH*260*SW];    // ~105 MB (half-spectrum)
__device__ float2 g_tw[NP];                      // e^{-2*pi*i*n/260}
__device__ float  g_w9[C2*9];
__device__ float  g_sig[C2];

// compile-time buffer selector: 0=g_ln, 1=g_h1, 2=g_x2, -1=external pointer
template<int SEL>
__device__ __forceinline__ float* gbuf(const float* ext){
    if (SEL == 0) return g_ln;
    if (SEL == 1) return g_h1;
    if (SEL == 2) return g_x2;
    return (float*)ext;
}

__device__ __forceinline__ float gelu_f(float x){
    return 0.5f * x * (1.0f + erff(x * 0.70710678118654752440f));
}

// ---------------- init: twiddles + per-channel softmax/sigma ----------------
__global__ void init_kernel(const float* __restrict__ conv_w,
                            const float* __restrict__ conv_sigma){
    int tid = threadIdx.x;
    if (tid < NP){
        double ang = -2.0 * 3.14159265358979323846 * (double)tid / (double)NP;
        double s, c;
        sincos(ang, &s, &c);
        g_tw[tid] = make_float2((float)c, (float)s);
    }
    for (int ch = tid; ch < C2; ch += blockDim.x){
        float w[9];
        float m = -1e30f;
        #pragma unroll
        for (int i=0;i<9;i++){ w[i] = conv_w[ch*9+i]; m = fmaxf(m, w[i]); }
        float ssum = 0.f;
        #pragma unroll
        for (int i=0;i<9;i++){ w[i] = expf(w[i]-m); ssum += w[i]; }
        float inv = 1.f/ssum;
        #pragma unroll
        for (int i=0;i<9;i++) g_w9[ch*9+i] = w[i]*inv;
        float sp = conv_sigma[ch];
        g_sig[ch] = 1.f/(1.f + expf(9.f - sp)) + 1e-5f;
    }
}

// ---------------- channels-first LayerNorm: src -> g_ln ----------------
template<int XSEL>
__global__ void ln_kernel(const float* __restrict__ xext,
                          const float* __restrict__ w,
                          const float* __restrict__ b){
    const float* x = gbuf<XSEL>(xext);
    int pi = blockIdx.x*blockDim.x + threadIdx.x;
    if (pi >= BB*PIX) return;
    int bb = pi >> 16;
    int p  = pi & (PIX-1);
    const float* xb = x + (size_t)bb*CC*PIX + p;
    float s=0.f, s2=0.f;
    #pragma unroll 4
    for (int c=0;c<CC;c++){ float v = xb[(size_t)c*PIX]; s += v; s2 += v*v; }
    float mu  = s * (1.f/CC);
    float var = s2 * (1.f/CC) - mu*mu;
    float inv = rsqrtf(var + 1e-5f);
    float* ob = g_ln + (size_t)bb*CC*PIX + p;
    #pragma unroll 4
    for (int c=0;c<CC;c++){
        float v = xb[(size_t)c*PIX];
        ob[(size_t)c*PIX] = (v-mu)*inv*w[c] + b[c];
    }
}

// ---------------- 1x1 conv as tiled SGEMM (vectorized) ----------------
// MODE 0: out = gelu(acc + bias);  MODE 1: out = acc + bias + res
template<int CIN, int COUT, int MODE, int XSEL, int RSEL, int OSEL>
__global__ void gemm_kernel(const float* __restrict__ Xext,
                            const float* __restrict__ W,
                            const float* __restrict__ bias,
                            const float* __restrict__ Rext,
                            float* __restrict__ Oext){
    const float* X   = gbuf<XSEL>(Xext);
    const float* res = gbuf<RSEL>(Rext);
    float*       out = gbuf<OSEL>(Oext);
    const int TP=128, TO=32, KC=16;
    __shared__ float Xs[KC][TP];
    __shared__ float Ws[KC][TO];
    int bb = blockIdx.z;
    int p0 = blockIdx.x*TP;
    int o0 = blockIdx.y*TO;
    int tid = threadIdx.x;       // 256
    int lane = tid & 31, warp = tid >> 5;
    float acc[4][4];
    #pragma unroll
    for (int j=0;j<4;j++)
        #pragma unroll
        for (int i=0;i<4;i++) acc[j][i]=0.f;

    const float* Xb = X + (size_t)bb*CIN*PIX + p0;
    for (int kc=0; kc<CIN; kc+=KC){
        #pragma unroll
        for (int ii=0; ii<2; ii++){
            int idx = tid + 256*ii;
            int k = idx >> 5, c4 = idx & 31;
            float4 v = *(const float4*)(Xb + (size_t)(kc+k)*PIX + c4*4);
            *(float4*)&Xs[k][c4*4] = v;
        }
        #pragma unroll
        for (int ii=0; ii<2; ii++){
            int idx = tid + 256*ii;
            int o = idx & 31, k = idx >> 5;
            Ws[k][o] = W[(size_t)(o0+o)*CIN + kc + k];
        }
        __syncthreads();
        #pragma unroll
        for (int k=0;k<KC;k++){
            float4 xv = *(const float4*)&Xs[k][lane*4];
            float4 wv = *(const float4*)&Ws[k][warp*4];
            float xa[4]={xv.x,xv.y,xv.z,xv.w};
            float wa[4]={wv.x,wv.y,wv.z,wv.w};
            #pragma unroll
            for (int j=0;j<4;j++)
                #pragma unroll
                for (int i=0;i<4;i++)
                    acc[j][i] += xa[i]*wa[j];
        }
        __syncthreads();
    }
    #pragma unroll
    for (int j=0;j<4;j++){
        int o = o0 + warp*4 + j;
        float bj = bias[o];
        size_t oidx = ((size_t)(bb*COUT + o))*PIX + p0 + lane*4;
        float4 v;
        v.x = acc[j][0]+bj; v.y = acc[j][1]+bj; v.z = acc[j][2]+bj; v.w = acc[j][3]+bj;
        if (MODE==0){
            v.x=gelu_f(v.x); v.y=gelu_f(v.y); v.z=gelu_f(v.z); v.w=gelu_f(v.w);
        } else {
            float4 r = *(const float4*)(res + oidx);
            v.x+=r.x; v.y+=r.y; v.z+=r.z; v.w+=r.w;
        }
        *(float4*)(out + oidx) = v;
    }
}

// ---------------- FFT core: 260 = 13 * 20 Cooley-Tukey, twiddle recurrence ----------------
// Stage A: A[n2*20+k1] = sum_{n1<20} x[13*n1+n2] * W260^{13*n1*k1}
// Stage C: X[k]        = sum_{n2<13} A[n2*20 + k%20] * W260^{n2*k}

__device__ __forceinline__ void stageA(const float2* __restrict__ xin,
                                       float2* __restrict__ As,
                                       const float2* __restrict__ tw20s,
                                       int lane, int stride, bool inv){
    for (int o=lane;o<NP;o+=stride){
        int n2=o/20, k1=o-20*n2;
        float2 t1 = tw20s[k1];
        if (inv) t1.y = -t1.y;
        float tx=1.f, ty=0.f, sx=0.f, sy=0.f;
        #pragma unroll
        for (int n1=0;n1<20;n1++){
            float2 v = xin[13*n1+n2];
            sx += v.x*tx - v.y*ty;
            sy += v.x*ty + v.y*tx;
            float nt = tx*t1.x - ty*t1.y;
            ty = tx*t1.y + ty*t1.x;
            tx = nt;
        }
        As[o] = make_float2(sx,sy);
    }
}

__device__ __forceinline__ float2 stageC_one(const float2* __restrict__ As,
                                             const float2* __restrict__ tws,
                                             int k, bool inv){
    int k1 = k%20;
    float2 t1 = tws[k];
    if (inv) t1.y = -t1.y;
    float tx=1.f, ty=0.f, sx=0.f, sy=0.f;
    #pragma unroll
    for (int n2=0;n2<13;n2++){
        float2 a = As[n2*20+k1];
        sx += a.x*tx - a.y*ty;
        sy += a.x*ty + a.y*tx;
        float nt = tx*t1.x - ty*t1.y;
        ty = tx*t1.y + ty*t1.x;
        tx = nt;
    }
    return make_float2(sx,sy);
}

// ---------------- forward row FFT: two real rows packed per complex FFT ----------------
__global__ void fft_rows_fwd_packed(){
    int pair = blockIdx.x;   // 0..129
    int ch   = blockIdx.y;   // 0..383
    __shared__ float2 xin[NP], As[NP], tws[NP], tw20s[20];
    int tid = threadIdx.x;   // 64
    for (int i=tid;i<NP;i+=64) tws[i]=g_tw[i];
    if (tid<20) tw20s[tid]=g_tw[13*tid];
    int r0 = 2*pair, r1 = r0+1;
    int s0 = min(max(r0-2,0),HH-1), s1 = min(max(r1-2,0),HH-1);
    const float* p0r = g_h1 + ((size_t)ch*HH + s0)*WW;
    const float* p1r = g_h1 + ((size_t)ch*HH + s1)*WW;
    for (int i=tid;i<NP;i+=64){
        int sc = min(max(i-2,0),WW-1);
        xin[i] = make_float2(p0r[sc], p1r[sc]);
    }
    __syncthreads();
    stageA(xin, As, tw20s, tid, 64, false);
    __syncthreads();
    float2* o0 = g_spec + ((size_t)ch*260 + r0)*SW;
    float2* o1 = g_spec + ((size_t)ch*260 + r1)*SW;
    for (int k=tid;k<=130;k+=64){
        float2 Zk = stageC_one(As, tws, k, false);
        int km = (260-k)%260;
        float2 Zm = stageC_one(As, tws, km, false);
        // unpack: A=(Z[k]+conj(Z[-k]))/2, B=(Z[k]-conj(Z[-k]))/(2i)
        o0[k] = make_float2(0.5f*(Zk.x+Zm.x), 0.5f*(Zk.y-Zm.y));
        o1[k] = make_float2(0.5f*(Zk.y+Zm.y), 0.5f*(Zm.x-Zk.x));
    }
}

// ---------------- column FFT over half-spectrum; DIR>0 also applies filter ----------------
template<int DIR>
__global__ void fft_cols_k(){
    int k0 = blockIdx.x*8;   // 17 blocks cover 131 columns
    int ch = blockIdx.y;
    __shared__ float2 cs[8][NP];
    __shared__ float2 As2[8][NP];
    __shared__ float2 tws[NP], tw20s[20];
    __shared__ float ws[10];
    int tid = threadIdx.x;   // 256
    for (int i=tid;i<NP;i+=256) tws[i]=g_tw[i];
    if (tid<20) tw20s[tid]=g_tw[13*tid];
    if (DIR>0){
        int c2 = ch % C2;
        if (tid<9) ws[tid]=g_w9[c2*9+tid];
        if (tid==9) ws[9]=g_sig[c2];
    }
    float2* base = g_spec + (size_t)ch*260*SW + k0;
    int ncols = 131 - k0; if (ncols>8) ncols=8;
    __syncthreads();
    for (int idx=tid; idx<260*8; idx+=256){
        int r=idx>>3, c=idx&7;
        if (c<ncols) cs[c][r] = base[(size_t)r*SW + c];
    }
    __syncthreads();
    int c = tid>>5, lane = tid&31;
    if (c < ncols){
        stageA(cs[c], As2[c], tw20s, lane, 32, DIR<0);
        __syncwarp();
        int k = k0 + c;
        float2 rp0, rp1, rp2; float sg = 0.f;
        if (DIR>0){
            float2 ev = tws[k];
            rp0 = make_float2(ws[0]*ev.x + ws[1] + ws[2]*ev.x, -ws[0]*ev.y + ws[2]*ev.y);
            rp1 = make_float2(ws[3]*ev.x + ws[4] + ws[5]*ev.x, -ws[3]*ev.y + ws[5]*ev.y);
            rp2 = make_float2(ws[6]*ev.x + ws[7] + ws[8]*ev.x, -ws[6]*ev.y + ws[8]*ev.y);
            sg = ws[9];
        }
        for (int u=lane;u<260;u+=32){
            float2 acc = stageC_one(As2[c], tws, u, DIR<0);
            if (DIR>0){
                float2 eu = tws[u];
                // FB = conj(eu)*rp0 + rp1 + eu*rp2
                float fbx = eu.x*rp0.x + eu.y*rp0.y + rp1.x + eu.x*rp2.x - eu.y*rp2.y;
                float fby = eu.x*rp0.y - eu.y*rp0.x + rp1.y + eu.x*rp2.y + eu.y*rp2.x;
                float denom = fbx*fbx + fby*fby + sg;
                float scale = 1.0f/(SPECN_F*denom);
                float hx = (fbx+sg)*scale, hy = -fby*scale;
                acc = make_float2(acc.x*hx - acc.y*hy, acc.x*hy + acc.y*hx);
            }
            cs[c][u] = acc;
        }
    }
    __syncthreads();
    for (int idx=tid; idx<260*8; idx+=256){
        int r=idx>>3, cc=idx&7;
        if (cc<ncols) base[(size_t)r*SW + cc] = cs[cc][r];
    }
}

// ---------------- inverse row FFT: two real output rows per complex inverse FFT ----------------
// After fft_cols_k<-1>, spec[ch][u][k] = Y_u[k] (k-spectrum of real spatial row u),
// so the missing k>130 half comes from the SAME row: Y_u[k] = conj(Y_u[260-k]).
__global__ void fft_rows_inv_packed(){
    int pair = blockIdx.x;   // 0..127
    int ch   = blockIdx.y;
    __shared__ float2 zin[NP], As[NP], tws[NP], tw20s[20];
    int tid = threadIdx.x;   // 64
    for (int i=tid;i<NP;i+=64) tws[i]=g_tw[i];
    if (tid<20) tw20s[tid]=g_tw[13*tid];
    int u0 = 2 + 2*pair, u1 = u0+1;   // padded output rows
    const float2* su0 = g_spec + ((size_t)ch*260 + u0)*SW;
    const float2* su1 = g_spec + ((size_t)ch*260 + u1)*SW;
    // z[k] = Y_u0[k] + i*Y_u1[k]
    for (int k=tid;k<=130;k+=64){
        float2 a = su0[k], b = su1[k];
        zin[k] = make_float2(a.x - b.y, a.y + b.x);
    }
    // k>130: Y_u[k] = conj(Y_u[260-k]) -> z[k] = conj(a) + i*conj(b)
    for (int k=131+tid;k<260;k+=64){
        float2 a = su0[260-k], b = su1[260-k];
        zin[k] = make_float2(a.x + b.y, b.x - a.y);
    }
    __syncthreads();
    stageA(zin, As, tw20s, tid, 64, true);
    __syncthreads();
    float* o0 = g_h1 + ((size_t)ch*HH + (u0-2))*WW;
    float* o1 = g_h1 + ((size_t)ch*HH + (u1-2))*WW;
    for (int jj=tid;jj<WW;jj+=64){
        float2 y = stageC_one(As, tws, jj+2, true);
        o0[jj] = gelu_f(y.x);
        o1[jj] = gelu_f(y.y);
    }
}

// ---------------- launcher: kernel launches ONLY ----------------
extern "C" void kernel_launch(void* const* d_in, const int* in_sizes, int n_in,
                              void* d_out, int out_size){
    const float* x         = (const float*)d_in[0];
    const float* ln1_w     = (const float*)d_in[1];
    const float* ln1_b     = (const float*)d_in[2];
    const float* w1a       = (const float*)d_in[3];
    const float* b1a       = (const float*)d_in[4];
    const float* conv_w    = (const float*)d_in[5];
    const float* conv_sig  = (const float*)d_in[6];
    const float* w1b       = (const float*)d_in[7];
    const float* b1b       = (const float*)d_in[8];
    const float* ln2_w     = (const float*)d_in[9];
    const float* ln2_b     = (const float*)d_in[10];
    const float* w2a       = (const float*)d_in[11];
    const float* b2a       = (const float*)d_in[12];
    const float* w2b       = (const float*)d_in[13];
    const float* b2b       = (const float*)d_in[14];
    float* out = (float*)d_out;

    init_kernel<<<1, 260>>>(conv_w, conv_sig);

    // branch 1: LN -> expand+gelu -> converse2d -> gelu -> project + residual
    ln_kernel<-1><<<(BB*PIX)/256, 256>>>(x, ln1_w, ln1_b);
    gemm_kernel<CC, C2, 0, 0, 0, 1><<<dim3(PIX/128, C2/32, BB), 256>>>(
        nullptr, w1a, b1a, nullptr, nullptr);

    fft_rows_fwd_packed<<<dim3(130, NCH), 64>>>();
    fft_cols_k<1><<<dim3(17, NCH), 256>>>();
    fft_cols_k<-1><<<dim3(17, NCH), 256>>>();
    fft_rows_inv_packed<<<dim3(128, NCH), 64>>>();

    gemm_kernel<C2, CC, 1, 1, -1, 2><<<dim3(PIX/128, CC/32, BB), 256>>>(
        nullptr, w1b, b1b, x, nullptr);

    // branch 2: LN -> expand+gelu -> project + residual
    ln_kernel<2><<<(BB*PIX)/256, 256>>>(nullptr, ln2_w, ln2_b);
    gemm_kernel<CC, C2, 0, 0, 0, 1><<<dim3(PIX/128, C2/32, BB), 256>>>(
        nullptr, w2a, b2a, nullptr, nullptr);
    gemm_kernel<C2, CC, 1, 1, 2, -1><<<dim3(PIX/128, CC/32, BB), 256>>>(
        nullptr, w2b, b2b, nullptr, out);
}

// round 6
// speedup vs baseline: 2.3497x; 1.1952x over previous
#include <cuda_runtime.h>
#include <math.h>

// ---------------- problem constants ----------------
#define BB 2
#define CC 96
#define C2 192
#define HH 256
#define WW 256
#define PIX (HH*WW)          // 65536
#define NP 260               // padded size (256 + 2*2)
#define SW 132               // spectral row stride (131 stored, Hermitian half)
#define NCH (BB*C2)          // 384
#define SPECN_F 67600.0f     // 260*260

// ---------------- scratch (static device globals; no runtime alloc) -------------
__device__ float  g_ln[(size_t)BB*CC*PIX];
__device__ float  g_h1[(size_t)BB*C2*PIX];
__device__ float  g_x2[(size_t)BB*CC*PIX];
__device__ float2 g_spec[(size_t)NCH*260*SW];    // ~105 MB (half-spectrum)
__device__ float2 g_tw[NP];                      // e^{-2*pi*i*n/260}
__device__ float  g_w9[C2*9];
__device__ float  g_sig[C2];

// compile-time buffer selector: 0=g_ln, 1=g_h1, 2=g_x2, -1=external pointer
template<int SEL>
__device__ __forceinline__ float* gbuf(const float* ext){
    if (SEL == 0) return g_ln;
    if (SEL == 1) return g_h1;
    if (SEL == 2) return g_x2;
    return (float*)ext;
}

__device__ __forceinline__ float gelu_f(float x){
    return 0.5f * x * (1.0f + erff(x * 0.70710678118654752440f));
}

// ---------------- complex helpers ----------------
__device__ __forceinline__ float2 cmul(float2 a, float2 b){
    return make_float2(a.x*b.x - a.y*b.y, a.x*b.y + a.y*b.x);
}
__device__ __forceinline__ float2 cmac(float2 s, float2 a, float2 t){
    s.x += a.x*t.x - a.y*t.y;
    s.y += a.x*t.y + a.y*t.x;
    return s;
}
__device__ __forceinline__ float2 cadd(float2 a, float2 b){ return make_float2(a.x+b.x, a.y+b.y); }
__device__ __forceinline__ float2 csub(float2 a, float2 b){ return make_float2(a.x-b.x, a.y-b.y); }

// ---------------- init: twiddles + per-channel softmax/sigma ----------------
__global__ void init_kernel(const float* __restrict__ conv_w,
                            const float* __restrict__ conv_sigma){
    int tid = threadIdx.x;
    if (tid < NP){
        double ang = -2.0 * 3.14159265358979323846 * (double)tid / (double)NP;
        double s, c;
        sincos(ang, &s, &c);
        g_tw[tid] = make_float2((float)c, (float)s);
    }
    for (int ch = tid; ch < C2; ch += blockDim.x){
        float w[9];
        float m = -1e30f;
        #pragma unroll
        for (int i=0;i<9;i++){ w[i] = conv_w[ch*9+i]; m = fmaxf(m, w[i]); }
        float ssum = 0.f;
        #pragma unroll
        for (int i=0;i<9;i++){ w[i] = expf(w[i]-m); ssum += w[i]; }
        float inv = 1.f/ssum;
        #pragma unroll
        for (int i=0;i<9;i++) g_w9[ch*9+i] = w[i]*inv;
        float sp = conv_sigma[ch];
        g_sig[ch] = 1.f/(1.f + expf(9.f - sp)) + 1e-5f;
    }
}

// ---------------- channels-first LayerNorm: src -> g_ln ----------------
template<int XSEL>
__global__ void ln_kernel(const float* __restrict__ xext,
                          const float* __restrict__ w,
                          const float* __restrict__ b){
    const float* x = gbuf<XSEL>(xext);
    int pi = blockIdx.x*blockDim.x + threadIdx.x;
    if (pi >= BB*PIX) return;
    int bb = pi >> 16;
    int p  = pi & (PIX-1);
    const float* xb = x + (size_t)bb*CC*PIX + p;
    float s=0.f, s2=0.f;
    #pragma unroll 4
    for (int c=0;c<CC;c++){ float v = xb[(size_t)c*PIX]; s += v; s2 += v*v; }
    float mu  = s * (1.f/CC);
    float var = s2 * (1.f/CC) - mu*mu;
    float inv = rsqrtf(var + 1e-5f);
    float* ob = g_ln + (size_t)bb*CC*PIX + p;
    #pragma unroll 4
    for (int c=0;c<CC;c++){
        float v = xb[(size_t)c*PIX];
        ob[(size_t)c*PIX] = (v-mu)*inv*w[c] + b[c];
    }
}

// ---------------- 1x1 conv as tiled SGEMM (vectorized) ----------------
// MODE 0: out = gelu(acc + bias);  MODE 1: out = acc + bias + res
template<int CIN, int COUT, int MODE, int XSEL, int RSEL, int OSEL>
__global__ void gemm_kernel(const float* __restrict__ Xext,
                            const float* __restrict__ W,
                            const float* __restrict__ bias,
                            const float* __restrict__ Rext,
                            float* __restrict__ Oext){
    const float* X   = gbuf<XSEL>(Xext);
    const float* res = gbuf<RSEL>(Rext);
    float*       out = gbuf<OSEL>(Oext);
    const int TP=128, TO=32, KC=16;
    __shared__ float Xs[KC][TP];
    __shared__ float Ws[KC][TO];
    int bb = blockIdx.z;
    int p0 = blockIdx.x*TP;
    int o0 = blockIdx.y*TO;
    int tid = threadIdx.x;       // 256
    int lane = tid & 31, warp = tid >> 5;
    float acc[4][4];
    #pragma unroll
    for (int j=0;j<4;j++)
        #pragma unroll
        for (int i=0;i<4;i++) acc[j][i]=0.f;

    const float* Xb = X + (size_t)bb*CIN*PIX + p0;
    for (int kc=0; kc<CIN; kc+=KC){
        #pragma unroll
        for (int ii=0; ii<2; ii++){
            int idx = tid + 256*ii;
            int k = idx >> 5, c4 = idx & 31;
            float4 v = *(const float4*)(Xb + (size_t)(kc+k)*PIX + c4*4);
            *(float4*)&Xs[k][c4*4] = v;
        }
        #pragma unroll
        for (int ii=0; ii<2; ii++){
            int idx = tid + 256*ii;
            int o = idx & 31, k = idx >> 5;
            Ws[k][o] = W[(size_t)(o0+o)*CIN + kc + k];
        }
        __syncthreads();
        #pragma unroll
        for (int k=0;k<KC;k++){
            float4 xv = *(const float4*)&Xs[k][lane*4];
            float4 wv = *(const float4*)&Ws[k][warp*4];
            float xa[4]={xv.x,xv.y,xv.z,xv.w};
            float wa[4]={wv.x,wv.y,wv.z,wv.w};
            #pragma unroll
            for (int j=0;j<4;j++)
                #pragma unroll
                for (int i=0;i<4;i++)
                    acc[j][i] += xa[i]*wa[j];
        }
        __syncthreads();
    }
    #pragma unroll
    for (int j=0;j<4;j++){
        int o = o0 + warp*4 + j;
        float bj = bias[o];
        size_t oidx = ((size_t)(bb*COUT + o))*PIX + p0 + lane*4;
        float4 v;
        v.x = acc[j][0]+bj; v.y = acc[j][1]+bj; v.z = acc[j][2]+bj; v.w = acc[j][3]+bj;
        if (MODE==0){
            v.x=gelu_f(v.x); v.y=gelu_f(v.y); v.z=gelu_f(v.z); v.w=gelu_f(v.w);
        } else {
            float4 r = *(const float4*)(res + oidx);
            v.x+=r.x; v.y+=r.y; v.z+=r.z; v.w+=r.w;
        }
        *(float4*)(out + oidx) = v;
    }
}

// ---------------- FFT core: 260 = 20 x 13 (13-pt DFTs then radix-4 20-pt stage) --------
// n = 20a + b (a<13, b<20), k = output index
// Stage A2: A2[13b+k2] = sum_{a<13} z[20a+b] * W13^{a*k2},  W13 = W260^20
// Stage C2: X[k] = sum_b A2[13b + (k%13)] * W260^{b*k}
//   radix-4 over b (W260^65 = -i): quads {q, q+65, q+130, q+195}, q<65 share data.

__device__ __forceinline__ void stageA2(const float2* __restrict__ z,
                                        float2* __restrict__ A2,
                                        const float2* __restrict__ tws,
                                        int lane, int stride, bool inv){
    for (int o=lane;o<NP;o+=stride){
        int b = o/13, k2 = o - 13*b;
        float2 t1 = tws[20*k2];
        if (inv) t1.y = -t1.y;
        float2 t = make_float2(1.f,0.f);
        float2 s = make_float2(0.f,0.f);
        #pragma unroll
        for (int a=0;a<13;a++){
            float2 v = z[20*a + b];
            s = cmac(s, v, t);
            t = cmul(t, t1);
        }
        A2[o] = s;   // o == 13b + k2
    }
}

// compute outputs X[q + 65j], j=0..3
__device__ __forceinline__ void stageC2_quad(const float2* __restrict__ A2,
                                             const float2* __restrict__ tws,
                                             int q, bool inv, float2 X[4]){
    int k2 = q % 13;
    float2 t1 = tws[q]; if (inv) t1.y = -t1.y;
    float2 t2 = cmul(t1,t1);
    float2 u  = cmul(t2,t2);     // t1^4
    float2 S0=make_float2(0,0), S1=make_float2(0,0), S2=make_float2(0,0), S3=make_float2(0,0);
    float2 t = make_float2(1.f,0.f);
    #pragma unroll
    for (int m=0;m<5;m++){
        const float2* base = A2 + (4*m)*13 + k2;
        float2 v0 = base[0], v1 = base[13], v2 = base[26], v3 = base[39];
        S0 = cmac(S0, v0, t);
        S1 = cmac(S1, v1, t);
        S2 = cmac(S2, v2, t);
        S3 = cmac(S3, v3, t);
        t = cmul(t, u);
    }
    float2 T1 = cmul(t1, S1);
    float2 T2 = cmul(t2, S2);
    float2 t3 = cmul(t2, t1);
    float2 T3 = cmul(t3, S3);
    float2 E0 = cadd(S0, T2), E1 = csub(S0, T2);
    float2 O0 = cadd(T1, T3), O1 = csub(T1, T3);
    X[0] = cadd(E0, O0);
    X[2] = csub(E0, O0);
    if (!inv){   // omega = -i
        X[1] = make_float2(E1.x + O1.y, E1.y - O1.x);
        X[3] = make_float2(E1.x - O1.y, E1.y + O1.x);
    } else {     // omega = +i
        X[1] = make_float2(E1.x - O1.y, E1.y + O1.x);
        X[3] = make_float2(E1.x + O1.y, E1.y - O1.x);
    }
}

// ---------------- forward row FFT: two real rows packed per complex FFT ----------------
__global__ void fft_rows_fwd_packed(){
    int pair = blockIdx.x;   // 0..129
    int ch   = blockIdx.y;   // 0..383
    __shared__ float2 xin[NP], As[NP], tws[NP];
    int tid = threadIdx.x;   // 64
    for (int i=tid;i<NP;i+=64) tws[i]=g_tw[i];
    int r0 = 2*pair, r1 = r0+1;
    int s0 = min(max(r0-2,0),HH-1), s1 = min(max(r1-2,0),HH-1);
    const float* p0r = g_h1 + ((size_t)ch*HH + s0)*WW;
    const float* p1r = g_h1 + ((size_t)ch*HH + s1)*WW;
    for (int i=tid;i<NP;i+=64){
        int sc = min(max(i-2,0),WW-1);
        xin[i] = make_float2(p0r[sc], p1r[sc]);
    }
    __syncthreads();
    stageA2(xin, As, tws, tid, 64, false);
    __syncthreads();
    for (int q=tid;q<65;q+=64){
        float2 X[4];
        stageC2_quad(As, tws, q, false, X);
        xin[q]      = X[0];
        xin[q+65]   = X[1];
        xin[q+130]  = X[2];
        xin[q+195]  = X[3];
    }
    __syncthreads();
    float2* o0 = g_spec + ((size_t)ch*260 + r0)*SW;
    float2* o1 = g_spec + ((size_t)ch*260 + r1)*SW;
    for (int k=tid;k<=130;k+=64){
        float2 Zk = xin[k];
        float2 Zm = xin[(260-k)%260];
        // unpack: A=(Z[k]+conj(Z[-k]))/2, B=(Z[k]-conj(Z[-k]))/(2i)
        o0[k] = make_float2(0.5f*(Zk.x+Zm.x), 0.5f*(Zk.y-Zm.y));
        o1[k] = make_float2(0.5f*(Zk.y+Zm.y), 0.5f*(Zm.x-Zk.x));
    }
}

// ---------------- fused column pass: fwd col FFT + filter + inv col FFT ----------------
__global__ void fft_cols_fused(){
    int k0 = blockIdx.x*8;   // 17 blocks cover 131 columns
    int ch = blockIdx.y;
    __shared__ float2 cs[8][NP];
    __shared__ float2 As2[8][NP];
    __shared__ float2 tws[NP];
    __shared__ float ws[10];
    int tid = threadIdx.x;   // 256
    for (int i=tid;i<NP;i+=256) tws[i]=g_tw[i];
    {
        int c2ch = ch % C2;
        if (tid<9) ws[tid]=g_w9[c2ch*9+tid];
        if (tid==9) ws[9]=g_sig[c2ch];
    }
    float2* base = g_spec + (size_t)ch*260*SW + k0;
    int ncols = 131 - k0; if (ncols>8) ncols=8;
    __syncthreads();
    for (int idx=tid; idx<260*8; idx+=256){
        int r=idx>>3, c=idx&7;
        if (c<ncols) cs[c][r] = base[(size_t)r*SW + c];
    }
    __syncthreads();
    int c = tid>>5, lane = tid&31;
    if (c < ncols){
        // ---- forward column FFT ----
        stageA2(cs[c], As2[c], tws, lane, 32, false);
        __syncwarp();
        int k = k0 + c;
        float2 ev = tws[k];
        float2 rp0 = make_float2(ws[0]*ev.x + ws[1] + ws[2]*ev.x, -ws[0]*ev.y + ws[2]*ev.y);
        float2 rp1 = make_float2(ws[3]*ev.x + ws[4] + ws[5]*ev.x, -ws[3]*ev.y + ws[5]*ev.y);
        float2 rp2 = make_float2(ws[6]*ev.x + ws[7] + ws[8]*ev.x, -ws[6]*ev.y + ws[8]*ev.y);
        float sg = ws[9];
        for (int q=lane;q<65;q+=32){
            float2 X[4];
            stageC2_quad(As2[c], tws, q, false, X);
            #pragma unroll
            for (int j=0;j<4;j++){
                int u = q + 65*j;
                float2 eu = tws[u];
                // FB = conj(eu)*rp0 + rp1 + eu*rp2
                float fbx = eu.x*rp0.x + eu.y*rp0.y + rp1.x + eu.x*rp2.x - eu.y*rp2.y;
                float fby = eu.x*rp0.y - eu.y*rp0.x + rp1.y + eu.x*rp2.y + eu.y*rp2.x;
                float denom = fbx*fbx + fby*fby + sg;
                float scale = 1.0f/(SPECN_F*denom);
                float hx = (fbx+sg)*scale, hy = -fby*scale;
                float2 a = X[j];
                cs[c][u] = make_float2(a.x*hx - a.y*hy, a.x*hy + a.y*hx);
            }
        }
        __syncwarp();
        // ---- inverse column FFT ----
        stageA2(cs[c], As2[c], tws, lane, 32, true);
        __syncwarp();
        for (int q=lane;q<65;q+=32){
            float2 X[4];
            stageC2_quad(As2[c], tws, q, true, X);
            cs[c][q]     = X[0];
            cs[c][q+65]  = X[1];
            cs[c][q+130] = X[2];
            cs[c][q+195] = X[3];
        }
    }
    __syncthreads();
    for (int idx=tid; idx<260*8; idx+=256){
        int r=idx>>3, cc=idx&7;
        if (cc<ncols) base[(size_t)r*SW + cc] = cs[cc][r];
    }
}

// ---------------- inverse row FFT: two real output rows per complex inverse FFT --------
// After the fused col pass, spec[ch][u][k] = Y_u[k] (k-spectrum of real spatial row u):
// missing k>130 half from SAME row: Y_u[k] = conj(Y_u[260-k]).
__global__ void fft_rows_inv_packed(){
    int pair = blockIdx.x;   // 0..127
    int ch   = blockIdx.y;
    __shared__ float2 zin[NP], As[NP], tws[NP];
    int tid = threadIdx.x;   // 64
    for (int i=tid;i<NP;i+=64) tws[i]=g_tw[i];
    int u0 = 2 + 2*pair, u1 = u0+1;   // padded output rows
    const float2* su0 = g_spec + ((size_t)ch*260 + u0)*SW;
    const float2* su1 = g_spec + ((size_t)ch*260 + u1)*SW;
    // z[k] = Y_u0[k] + i*Y_u1[k]
    for (int k=tid;k<=130;k+=64){
        float2 a = su0[k], b = su1[k];
        zin[k] = make_float2(a.x - b.y, a.y + b.x);
    }
    for (int k=131+tid;k<260;k+=64){
        float2 a = su0[260-k], b = su1[260-k];
        zin[k] = make_float2(a.x + b.y, b.x - a.y);
    }
    __syncthreads();
    stageA2(zin, As, tws, tid, 64, true);
    __syncthreads();
    for (int q=tid;q<65;q+=64){
        float2 X[4];
        stageC2_quad(As, tws, q, true, X);
        zin[q]     = X[0];
        zin[q+65]  = X[1];
        zin[q+130] = X[2];
        zin[q+195] = X[3];
    }
    __syncthreads();
    float* o0 = g_h1 + ((size_t)ch*HH + (u0-2))*WW;
    float* o1 = g_h1 + ((size_t)ch*HH + (u1-2))*WW;
    for (int jj=tid;jj<WW;jj+=64){
        float2 y = zin[jj+2];
        o0[jj] = gelu_f(y.x);
        o1[jj] = gelu_f(y.y);
    }
}

// ---------------- launcher: kernel launches ONLY ----------------
extern "C" void kernel_launch(void* const* d_in, const int* in_sizes, int n_in,
                              void* d_out, int out_size){
    const float* x         = (const float*)d_in[0];
    const float* ln1_w     = (const float*)d_in[1];
    const float* ln1_b     = (const float*)d_in[2];
    const float* w1a       = (const float*)d_in[3];
    const float* b1a       = (const float*)d_in[4];
    const float* conv_w    = (const float*)d_in[5];
    const float* conv_sig  = (const float*)d_in[6];
    const float* w1b       = (const float*)d_in[7];
    const float* b1b       = (const float*)d_in[8];
    const float* ln2_w     = (const float*)d_in[9];
    const float* ln2_b     = (const float*)d_in[10];
    const float* w2a       = (const float*)d_in[11];
    const float* b2a       = (const float*)d_in[12];
    const float* w2b       = (const float*)d_in[13];
    const float* b2b       = (const float*)d_in[14];
    float* out = (float*)d_out;

    init_kernel<<<1, 260>>>(conv_w, conv_sig);

    // branch 1: LN -> expand+gelu -> converse2d -> gelu -> project + residual
    ln_kernel<-1><<<(BB*PIX)/256, 256>>>(x, ln1_w, ln1_b);
    gemm_kernel<CC, C2, 0, 0, 0, 1><<<dim3(PIX/128, C2/32, BB), 256>>>(
        nullptr, w1a, b1a, nullptr, nullptr);

    fft_rows_fwd_packed<<<dim3(130, NCH), 64>>>();
    fft_cols_fused<<<dim3(17, NCH), 256>>>();
    fft_rows_inv_packed<<<dim3(128, NCH), 64>>>();

    gemm_kernel<C2, CC, 1, 1, -1, 2><<<dim3(PIX/128, CC/32, BB), 256>>>(
        nullptr, w1b, b1b, x, nullptr);

    // branch 2: LN -> expand+gelu -> project + residual
    ln_kernel<2><<<(BB*PIX)/256, 256>>>(nullptr, ln2_w, ln2_b);
    gemm_kernel<CC, C2, 0, 0, 0, 1><<<dim3(PIX/128, C2/32, BB), 256>>>(
        nullptr, w2a, b2a, nullptr, nullptr);
    gemm_kernel<C2, CC, 1, 1, 2, -1><<<dim3(PIX/128, CC/32, BB), 256>>>(
        nullptr, w2b, b2b, nullptr, out);
}